// round 7
// baseline (speedup 1.0000x reference)
#include <cuda_runtime.h>
#include <cuda_bf16.h>
#include <stdint.h>

// Problem constants
#define NN   50000
#define EE   800000
#define GG   512
#define DIN  128
#define HH   64
#define LL   3
#define ZS   192              // L*H, row stride of z_cat and pool
#define BN_EPS 1e-5f

// ---------------- tiny device globals only (~1 KB total) ----------------
// NOTE: never passed as host-side kernel arguments (host sees the shadow
// symbol, not the device address). All access is from device code.
__device__ __align__(16) float g_stats[128];   // [0:64) sum, [64:128) sumsq
__device__ __align__(16) float g_ss[128];      // [0:64) scale, [64:128) shift
__device__ int g_is64;

// ---------------- helpers ----------------
__device__ __forceinline__ void red4(float* p, float4 v) {
    atomicAdd(reinterpret_cast<float4*>(p), v);   // native vector red (CC >= 9.0)
}

__device__ __forceinline__ long long ldidx(const void* p, long long i, int is64) {
    if (is64) return ((const long long*)p)[i];
    return (long long)((const int*)p)[i];
}

// int64 vs int32 index detection (first 16 int64-interpretations in range => int64)
__global__ void detect_kernel(const long long* ei) {
    if (threadIdx.x == 0) {
        int ok = 1;
        for (int i = 0; i < 16; i++) {
            long long v = ei[i];
            if (v < 0 || v >= NN) ok = 0;
        }
        g_is64 = ok;
    }
}

// zero g_stats via direct device-code symbol access (the R6 bug fix)
__global__ void zero_stats_kernel() {
    if (threadIdx.x < 128) g_stats[threadIdx.x] = 0.0f;
}

__global__ void zero_kernel(float* p, int n) {
    int i = blockIdx.x * 256 + threadIdx.x;
    for (; i < n; i += gridDim.x * 256) p[i] = 0.0f;
}

// ---------------- L0 projection: y0 = x @ W1 (128->64) ----------------
// Writes y0 into zc cols [64,128) and the agg init copy into cols [0,64).
// Block 256 = 64 nodes x 4 feature-groups; thread owns 1 node x 16 features.
__global__ void __launch_bounds__(256) gemm1_kernel(
    const float* __restrict__ x, const float* __restrict__ W1, float* zc)
{
    __shared__ float Ws[64 * 64];    // 16 KB weight chunk
    __shared__ float Xs[64 * 68];    // padded input chunk

    const int tid = threadIdx.x;
    const int fg = tid & 3;
    const int ns = tid >> 2;
    const int node0 = blockIdx.x * 64;

    float acc[16];
#pragma unroll
    for (int q = 0; q < 16; q++) acc[q] = 0.0f;

    for (int kc = 0; kc < DIN / 64; kc++) {
        __syncthreads();
        for (int i = tid; i < 64 * 16; i += 256)
            reinterpret_cast<float4*>(Ws)[i] =
                reinterpret_cast<const float4*>(W1 + kc * 64 * 64)[i];
        {
            int ln = tid >> 2, part = tid & 3;
            int gn = node0 + ln; if (gn >= NN) gn = NN - 1;
            const float4* zr = reinterpret_cast<const float4*>(
                x + (long long)gn * DIN + kc * 64);
            float4* br = reinterpret_cast<float4*>(Xs + ln * 68);
#pragma unroll
            for (int q = 0; q < 4; q++) br[part * 4 + q] = zr[part * 4 + q];
        }
        __syncthreads();
#pragma unroll 8
        for (int k = 0; k < 64; k++) {
            float v = Xs[ns * 68 + k];
            const float4* wr = reinterpret_cast<const float4*>(Ws + k * 64 + fg * 16);
            float4 w0 = wr[0], w1 = wr[1], w2 = wr[2], w3 = wr[3];
            acc[0]  += v * w0.x; acc[1]  += v * w0.y; acc[2]  += v * w0.z; acc[3]  += v * w0.w;
            acc[4]  += v * w1.x; acc[5]  += v * w1.y; acc[6]  += v * w1.z; acc[7]  += v * w1.w;
            acc[8]  += v * w2.x; acc[9]  += v * w2.y; acc[10] += v * w2.z; acc[11] += v * w2.w;
            acc[12] += v * w3.x; acc[13] += v * w3.y; acc[14] += v * w3.z; acc[15] += v * w3.w;
        }
    }

    int node = node0 + ns;
    if (node < NN) {
        float* row = zc + (long long)node * ZS;
        float4* yo = reinterpret_cast<float4*>(row + 64) + fg * 4;  // y0 @ cols 64..127
        float4* ao = reinterpret_cast<float4*>(row) + fg * 4;       // agg init @ cols 0..63
#pragma unroll
        for (int i = 0; i < 4; i++) {
            float4 r = make_float4(acc[i*4+0], acc[i*4+1], acc[i*4+2], acc[i*4+3]);
            yo[i] = r; ao[i] = r;
        }
    }
}

// ---------------- edge scatter: zc[dst, agg_col..] += zc[src, src_col..] ----------------
// 16 threads (one float4 each) per edge; rows stride ZS. Read/write columns
// are always disjoint, so no intra-kernel hazard.
__global__ void scatter_kernel(float* zc, int src_col, int agg_col,
                               const void* __restrict__ ei) {
    int gtid = blockIdx.x * 256 + threadIdx.x;
    int e = gtid >> 4;
    int c = gtid & 15;
    if (e >= EE) return;
    int is64 = g_is64;
    long long s = ldidx(ei, e, is64);
    long long d = ldidx(ei, (long long)EE + e, is64);
    float4 v = *reinterpret_cast<const float4*>(zc + s * ZS + src_col + c * 4);
    red4(zc + d * ZS + agg_col + c * 4, v);
}

// ---------------- L0 MLP tail: h = relu( relu(agg + b1) @ W2 + b2 ), in place ----------------
__global__ void __launch_bounds__(256) mlp0_kernel(
    float* zc, int col,
    const float* __restrict__ W2, const float* __restrict__ b1,
    const float* __restrict__ b2)
{
    __shared__ float Ws[64 * 64];
    __shared__ float Xs[64 * 68];

    const int tid = threadIdx.x;
    const int fg = tid & 3;
    const int ns = tid >> 2;
    const int node0 = blockIdx.x * 64;

    for (int i = tid; i < 64 * 16; i += 256)
        reinterpret_cast<float4*>(Ws)[i] = reinterpret_cast<const float4*>(W2)[i];
    {
        int ln = tid >> 2, part = tid & 3;
        int gn = node0 + ln; if (gn >= NN) gn = NN - 1;
        const float4* ar = reinterpret_cast<const float4*>(zc + (long long)gn * ZS + col);
        float4* br = reinterpret_cast<float4*>(Xs + ln * 68);
#pragma unroll
        for (int q = 0; q < 4; q++) {
            float4 a = ar[part * 4 + q];
            float4 bb = reinterpret_cast<const float4*>(b1)[part * 4 + q];
            br[part * 4 + q] = make_float4(
                fmaxf(a.x + bb.x, 0.0f), fmaxf(a.y + bb.y, 0.0f),
                fmaxf(a.z + bb.z, 0.0f), fmaxf(a.w + bb.w, 0.0f));
        }
    }
    __syncthreads();

    float acc[16];
#pragma unroll
    for (int i = 0; i < 4; i++) {
        float4 bb2 = reinterpret_cast<const float4*>(b2)[fg * 4 + i];
        acc[i*4+0] = bb2.x; acc[i*4+1] = bb2.y; acc[i*4+2] = bb2.z; acc[i*4+3] = bb2.w;
    }
#pragma unroll 8
    for (int k = 0; k < 64; k++) {
        float v = Xs[ns * 68 + k];
        const float4* wr = reinterpret_cast<const float4*>(Ws + k * 64 + fg * 16);
        float4 w0 = wr[0], w1 = wr[1], w2 = wr[2], w3 = wr[3];
        acc[0]  += v * w0.x; acc[1]  += v * w0.y; acc[2]  += v * w0.z; acc[3]  += v * w0.w;
        acc[4]  += v * w1.x; acc[5]  += v * w1.y; acc[6]  += v * w1.z; acc[7]  += v * w1.w;
        acc[8]  += v * w2.x; acc[9]  += v * w2.y; acc[10] += v * w2.z; acc[11] += v * w2.w;
        acc[12] += v * w3.x; acc[13] += v * w3.y; acc[14] += v * w3.z; acc[15] += v * w3.w;
    }

    int node = node0 + ns;
    if (node < NN) {
        float4* outp = reinterpret_cast<float4*>(zc + (long long)node * ZS + col) + fg * 4;
#pragma unroll
        for (int i = 0; i < 4; i++)
            outp[i] = make_float4(fmaxf(acc[i*4+0], 0.0f), fmaxf(acc[i*4+1], 0.0f),
                                  fmaxf(acc[i*4+2], 0.0f), fmaxf(acc[i*4+3], 0.0f));
    }
}

// ---------------- L1/L2 fused MLP: h = relu( relu(agg@W1 + b1) @ W2 + b2 ) ----------------
// Reads agg from zc col in_col, writes h to zc col out_col (may alias: block-local
// read-then-write over disjoint row sets is safe).
__global__ void __launch_bounds__(256) mlp2_kernel(
    float* zc, int in_col, int out_col,
    const float* __restrict__ W1, const float* __restrict__ b1,
    const float* __restrict__ W2, const float* __restrict__ b2)
{
    __shared__ float Ws[64 * 64];
    __shared__ float Xs[64 * 68];

    const int tid = threadIdx.x;
    const int fg = tid & 3;
    const int ns = tid >> 2;
    const int node0 = blockIdx.x * 64;

    // stage W1 + agg chunk
    for (int i = tid; i < 64 * 16; i += 256)
        reinterpret_cast<float4*>(Ws)[i] = reinterpret_cast<const float4*>(W1)[i];
    {
        int ln = tid >> 2, part = tid & 3;
        int gn = node0 + ln; if (gn >= NN) gn = NN - 1;
        const float4* ar = reinterpret_cast<const float4*>(zc + (long long)gn * ZS + in_col);
        float4* br = reinterpret_cast<float4*>(Xs + ln * 68);
#pragma unroll
        for (int q = 0; q < 4; q++) br[part * 4 + q] = ar[part * 4 + q];
    }
    __syncthreads();

    // phase 1: acc = agg @ W1
    float acc[16];
#pragma unroll
    for (int q = 0; q < 16; q++) acc[q] = 0.0f;
#pragma unroll 8
    for (int k = 0; k < 64; k++) {
        float v = Xs[ns * 68 + k];
        const float4* wr = reinterpret_cast<const float4*>(Ws + k * 64 + fg * 16);
        float4 w0 = wr[0], w1 = wr[1], w2 = wr[2], w3 = wr[3];
        acc[0]  += v * w0.x; acc[1]  += v * w0.y; acc[2]  += v * w0.z; acc[3]  += v * w0.w;
        acc[4]  += v * w1.x; acc[5]  += v * w1.y; acc[6]  += v * w1.z; acc[7]  += v * w1.w;
        acc[8]  += v * w2.x; acc[9]  += v * w2.y; acc[10] += v * w2.z; acc[11] += v * w2.w;
        acc[12] += v * w3.x; acc[13] += v * w3.y; acc[14] += v * w3.z; acc[15] += v * w3.w;
    }
    __syncthreads();   // phase-1 reads of Ws/Xs complete

    // h1 = relu(acc + b1) -> Xs ; stage W2 -> Ws
    {
        float4 bb = reinterpret_cast<const float4*>(b1)[fg * 4];
        float4 bb1 = reinterpret_cast<const float4*>(b1)[fg * 4 + 1];
        float4 bb2 = reinterpret_cast<const float4*>(b1)[fg * 4 + 2];
        float4 bb3 = reinterpret_cast<const float4*>(b1)[fg * 4 + 3];
        float4* hr = reinterpret_cast<float4*>(Xs + ns * 68 + fg * 16);
        hr[0] = make_float4(fmaxf(acc[0]+bb.x,0.f),  fmaxf(acc[1]+bb.y,0.f),
                            fmaxf(acc[2]+bb.z,0.f),  fmaxf(acc[3]+bb.w,0.f));
        hr[1] = make_float4(fmaxf(acc[4]+bb1.x,0.f), fmaxf(acc[5]+bb1.y,0.f),
                            fmaxf(acc[6]+bb1.z,0.f), fmaxf(acc[7]+bb1.w,0.f));
        hr[2] = make_float4(fmaxf(acc[8]+bb2.x,0.f), fmaxf(acc[9]+bb2.y,0.f),
                            fmaxf(acc[10]+bb2.z,0.f),fmaxf(acc[11]+bb2.w,0.f));
        hr[3] = make_float4(fmaxf(acc[12]+bb3.x,0.f),fmaxf(acc[13]+bb3.y,0.f),
                            fmaxf(acc[14]+bb3.z,0.f),fmaxf(acc[15]+bb3.w,0.f));
    }
    for (int i = tid; i < 64 * 16; i += 256)
        reinterpret_cast<float4*>(Ws)[i] = reinterpret_cast<const float4*>(W2)[i];
    __syncthreads();

    // phase 2: o = h1 @ W2 + b2
#pragma unroll
    for (int i = 0; i < 4; i++) {
        float4 bb2 = reinterpret_cast<const float4*>(b2)[fg * 4 + i];
        acc[i*4+0] = bb2.x; acc[i*4+1] = bb2.y; acc[i*4+2] = bb2.z; acc[i*4+3] = bb2.w;
    }
#pragma unroll 8
    for (int k = 0; k < 64; k++) {
        float v = Xs[ns * 68 + k];
        const float4* wr = reinterpret_cast<const float4*>(Ws + k * 64 + fg * 16);
        float4 w0 = wr[0], w1 = wr[1], w2 = wr[2], w3 = wr[3];
        acc[0]  += v * w0.x; acc[1]  += v * w0.y; acc[2]  += v * w0.z; acc[3]  += v * w0.w;
        acc[4]  += v * w1.x; acc[5]  += v * w1.y; acc[6]  += v * w1.z; acc[7]  += v * w1.w;
        acc[8]  += v * w2.x; acc[9]  += v * w2.y; acc[10] += v * w2.z; acc[11] += v * w2.w;
        acc[12] += v * w3.x; acc[13] += v * w3.y; acc[14] += v * w3.z; acc[15] += v * w3.w;
    }

    int node = node0 + ns;
    if (node < NN) {
        float4* outp = reinterpret_cast<float4*>(zc + (long long)node * ZS + out_col) + fg * 4;
#pragma unroll
        for (int i = 0; i < 4; i++)
            outp[i] = make_float4(fmaxf(acc[i*4+0], 0.0f), fmaxf(acc[i*4+1], 0.0f),
                                  fmaxf(acc[i*4+2], 0.0f), fmaxf(acc[i*4+3], 0.0f));
    }
}

// ---------------- batch-norm statistics over h slice ----------------
__global__ void stats_kernel(const float* __restrict__ h) {
    int f = threadIdx.x & 63;
    int rl = threadIdx.x >> 6;
    float s = 0.0f, q = 0.0f;
    for (int r = blockIdx.x * 4 + rl; r < NN; r += gridDim.x * 4) {
        float v = h[(long long)r * ZS + f];
        s += v;
        q += v * v;
    }
    atomicAdd(&g_stats[f], s);
    atomicAdd(&g_stats[64 + f], q);
}

__global__ void bn_finalize_kernel(const float* __restrict__ gam, const float* __restrict__ bet) {
    int f = threadIdx.x;
    float mean = g_stats[f] * (1.0f / NN);
    float var = g_stats[64 + f] * (1.0f / NN) - mean * mean;
    var = fmaxf(var, 0.0f);
    float sc = gam[f] * rsqrtf(var + BN_EPS);
    g_ss[f] = sc;
    g_ss[64 + f] = bet[f] - mean * sc;
}

// ---------------- BN apply (in place) + pool + optional copy (next layer's agg init) --------
__global__ void bn_apply_kernel(float* zc, int col_off, int copy_off,
                                const void* __restrict__ batch,
                                float* __restrict__ pool)
{
    int t = blockIdx.x * 256 + threadIdx.x;
    int n = t >> 4;
    int c = t & 15;
    if (n >= NN) return;
    int is64 = g_is64;
    float* row = zc + (long long)n * ZS;
    float4 h4 = *reinterpret_cast<float4*>(row + col_off + c * 4);
    float4 sc = *reinterpret_cast<const float4*>(g_ss + c * 4);
    float4 sh = *reinterpret_cast<const float4*>(g_ss + 64 + c * 4);
    float4 z;
    z.x = h4.x * sc.x + sh.x;
    z.y = h4.y * sc.y + sh.y;
    z.z = h4.z * sc.z + sh.z;
    z.w = h4.w * sc.w + sh.w;
    *reinterpret_cast<float4*>(row + col_off + c * 4) = z;
    if (copy_off >= 0)
        *reinterpret_cast<float4*>(row + copy_off + c * 4) = z;
    long long b = ldidx(batch, n, is64);
    red4(pool + b * ZS + col_off + c * 4, z);
}

// ---------------- launch ----------------
extern "C" void kernel_launch(void* const* d_in, const int* in_sizes, int n_in,
                              void* d_out, int out_size)
{
    const float* x     = (const float*)d_in[0];
    const void*  ei    = d_in[1];
    const void*  batch = d_in[2];
    const float* W1_0  = (const float*)d_in[3];
    const float* b1_0  = (const float*)d_in[4];
    const float* W2_0  = (const float*)d_in[5];
    const float* b2_0  = (const float*)d_in[6];
    const float* bn_g0 = (const float*)d_in[7];
    const float* bn_b0 = (const float*)d_in[8];
    const float* W1_r  = (const float*)d_in[9];
    const float* b1_r  = (const float*)d_in[10];
    const float* W2_r  = (const float*)d_in[11];
    const float* b2_r  = (const float*)d_in[12];
    const float* bn_gr = (const float*)d_in[13];
    const float* bn_br = (const float*)d_in[14];

    float* zc   = (float*)d_out;
    float* pool = zc + (long long)NN * ZS;

    const int gemm_grid = (NN + 63) / 64;
    const int scat_grid = (EE * 16 + 255) / 256;
    const int bn_grid   = (NN * 16 + 255) / 256;

    detect_kernel<<<1, 32>>>((const long long*)ei);
    zero_kernel<<<512, 256>>>(pool, GG * ZS);

    // ---- layer 0: project first (y0 @ cols 64..127, agg init @ cols 0..63) ----
    gemm1_kernel<<<gemm_grid, 256>>>(x, W1_0, zc);
    scatter_kernel<<<scat_grid, 256>>>(zc, 64, 0, ei);
    mlp0_kernel<<<gemm_grid, 256>>>(zc, 0, W2_0, b1_0, b2_0);
    zero_stats_kernel<<<1, 128>>>();
    stats_kernel<<<512, 256>>>(zc + 0);
    bn_finalize_kernel<<<1, 64>>>(bn_g0, bn_b0);
    bn_apply_kernel<<<bn_grid, 256>>>(zc, 0, 128, batch, pool);   // copy z0 -> cols 128 (L1 agg init)

    // ---- layer 1: agg in z-space @ cols 128..191, output z1 @ cols 64..127 ----
    scatter_kernel<<<scat_grid, 256>>>(zc, 0, 128, ei);
    mlp2_kernel<<<gemm_grid, 256>>>(zc, 128, 64, W1_r, b1_r, W2_r, b2_r);
    zero_stats_kernel<<<1, 128>>>();
    stats_kernel<<<512, 256>>>(zc + 64);
    bn_finalize_kernel<<<1, 64>>>(bn_gr, bn_br);
    bn_apply_kernel<<<bn_grid, 256>>>(zc, 64, 128, batch, pool);  // copy z1 -> cols 128 (L2 agg init)

    // ---- layer 2: agg @ cols 128..191, output z2 @ cols 128..191 (in place) ----
    scatter_kernel<<<scat_grid, 256>>>(zc, 64, 128, ei);
    mlp2_kernel<<<gemm_grid, 256>>>(zc, 128, 128,
                                    W1_r + (size_t)HH * HH, b1_r + HH,
                                    W2_r + (size_t)HH * HH, b2_r + HH);
    zero_stats_kernel<<<1, 128>>>();
    stats_kernel<<<512, 256>>>(zc + 128);
    bn_finalize_kernel<<<1, 64>>>(bn_gr + HH, bn_br + HH);
    bn_apply_kernel<<<bn_grid, 256>>>(zc, 128, -1, batch, pool);

    (void)in_sizes; (void)n_in; (void)out_size;
}

// round 8
// speedup vs baseline: 2.0074x; 2.0074x over previous
#include <cuda_runtime.h>
#include <cuda_bf16.h>
#include <stdint.h>

// Problem constants
#define NN   50000
#define EE   800000
#define GG   512
#define DIN  128
#define HH   64
#define LL   3
#define ZS   192              // L*H, row stride of z_cat and pool
#define BN_EPS 1e-5f

// ---------------- tiny device globals only (~1 KB; accessed from device code only) ----
__device__ __align__(16) float g_stats[128];   // [0:64) sum, [64:128) sumsq
__device__ __align__(16) float g_ss[128];      // [0:64) scale, [64:128) shift
__device__ int g_is64;

// ---------------- helpers ----------------
__device__ __forceinline__ void red4(float* p, float4 v) {
    atomicAdd(reinterpret_cast<float4*>(p), v);   // native vector red (CC >= 9.0)
}

__device__ __forceinline__ long long ldidx(const void* p, long long i, int is64) {
    if (is64) return ((const long long*)p)[i];
    return (long long)((const int*)p)[i];
}

// ---------------- setup: zero pool, zero stats, detect index dtype ----------------
__global__ void setup_kernel(float* pool, const long long* ei) {
    for (int i = blockIdx.x * 256 + threadIdx.x; i < GG * ZS; i += gridDim.x * 256)
        pool[i] = 0.0f;
    if (blockIdx.x == 0) {
        if (threadIdx.x < 128) g_stats[threadIdx.x] = 0.0f;
        if (threadIdx.x == 0) {
            int ok = 1;
            for (int i = 0; i < 16; i++) {
                long long v = ei[i];
                if (v < 0 || v >= NN) ok = 0;
            }
            g_is64 = ok;
        }
    }
}

// ======================= GEMM building blocks =======================
// Block: 128 threads, 64 nodes. Thread (ng = tid>>3, fg = tid&7) owns
// nodes ng*4..ng*4+3  x  features fg*8..fg*8+7  -> acc[32] registers.
// Xs: 64 rows x 68 stride (padded). Ws: 64x64.

__device__ __forceinline__ void stage_w(float* Ws, const float* __restrict__ W, int tid) {
    for (int i = tid; i < 1024; i += 128)
        reinterpret_cast<float4*>(Ws)[i] = reinterpret_cast<const float4*>(W)[i];
}

// stage 64 nodes x 64 floats from gx (row stride zstride) into Xs
__device__ __forceinline__ void stage_x(float* Xs, const float* __restrict__ gx,
                                        int zstride, int node0, int tid) {
    int row = tid >> 1, part = tid & 1;
    int gn = node0 + row; if (gn >= NN) gn = NN - 1;
    const float4* src = reinterpret_cast<const float4*>(gx + (long long)gn * zstride);
    float4* dst = reinterpret_cast<float4*>(Xs + row * 68);
#pragma unroll
    for (int q = 0; q < 8; q++) dst[part * 8 + q] = src[part * 8 + q];
}

// acc += Xs(64x64) @ Ws(64x64) for this thread's 4x8 tile
__device__ __forceinline__ void gemm_core(const float* Xs, const float* Ws,
                                          int ng, int fg, float* acc) {
#pragma unroll 8
    for (int k = 0; k < 64; k++) {
        const float4* wr = reinterpret_cast<const float4*>(Ws + k * 64 + fg * 8);
        float4 wa = wr[0], wb = wr[1];
#pragma unroll
        for (int i = 0; i < 4; i++) {
            float v = Xs[(ng * 4 + i) * 68 + k];
            acc[i*8+0] += v * wa.x; acc[i*8+1] += v * wa.y;
            acc[i*8+2] += v * wa.z; acc[i*8+3] += v * wa.w;
            acc[i*8+4] += v * wb.x; acc[i*8+5] += v * wb.y;
            acc[i*8+6] += v * wb.z; acc[i*8+7] += v * wb.w;
        }
    }
}

// per-block BN-stat partials for post-relu outputs o[32]; S = scratch >= 16*130 floats.
// All 128 threads must call. Caller syncs before (S may alias Ws/Xs).
__device__ __forceinline__ void stats_epi(float* S, const float* o,
                                          int ng, int fg, int node0, int tid) {
    float s[8], q[8];
#pragma unroll
    for (int j = 0; j < 8; j++) { s[j] = 0.0f; q[j] = 0.0f; }
#pragma unroll
    for (int i = 0; i < 4; i++) {
        if (node0 + ng * 4 + i < NN) {
#pragma unroll
            for (int j = 0; j < 8; j++) { float v = o[i*8+j]; s[j] += v; q[j] += v * v; }
        }
    }
#pragma unroll
    for (int j = 0; j < 8; j++) {
        S[ng * 130 + fg * 8 + j] = s[j];
        S[ng * 130 + 65 + fg * 8 + j] = q[j];
    }
    __syncthreads();
    int f = tid & 63, which = tid >> 6;
    float a = 0.0f;
#pragma unroll
    for (int g = 0; g < 16; g++) a += S[g * 130 + which * 65 + f];
    atomicAdd(&g_stats[which * 64 + f], a);
}

// ---------------- L0 projection: y0 = x @ W1 (128->64) ----------------
// y0 -> zc cols [64,128); agg-init copy -> cols [0,64).
__global__ void __launch_bounds__(128) gemm1_kernel(
    const float* __restrict__ x, const float* __restrict__ W1, float* zc)
{
    __shared__ float Ws[64 * 64];
    __shared__ float Xs[64 * 68];
    const int tid = threadIdx.x, fg = tid & 7, ng = tid >> 3;
    const int node0 = blockIdx.x * 64;

    float acc[32];
#pragma unroll
    for (int q = 0; q < 32; q++) acc[q] = 0.0f;

    for (int kc = 0; kc < 2; kc++) {
        __syncthreads();
        stage_w(Ws, W1 + kc * 64 * 64, tid);
        stage_x(Xs, x + kc * 64, DIN, node0, tid);
        __syncthreads();
        gemm_core(Xs, Ws, ng, fg, acc);
    }

#pragma unroll
    for (int i = 0; i < 4; i++) {
        int node = node0 + ng * 4 + i;
        if (node < NN) {
            float* row = zc + (long long)node * ZS;
            float4 r0 = make_float4(acc[i*8+0], acc[i*8+1], acc[i*8+2], acc[i*8+3]);
            float4 r1 = make_float4(acc[i*8+4], acc[i*8+5], acc[i*8+6], acc[i*8+7]);
            *reinterpret_cast<float4*>(row + 64 + fg * 8)     = r0;
            *reinterpret_cast<float4*>(row + 64 + fg * 8 + 4) = r1;
            *reinterpret_cast<float4*>(row + fg * 8)          = r0;
            *reinterpret_cast<float4*>(row + fg * 8 + 4)      = r1;
        }
    }
}

// ---------------- edge scatter: zc[dst, agg_col..] += zc[src, src_col..] ----------------
// 8 threads per edge, 32 B each (2 x float4). Read/write columns disjoint.
__global__ void scatter_kernel(float* zc, int src_col, int agg_col,
                               const void* __restrict__ ei) {
    int gtid = blockIdx.x * 256 + threadIdx.x;
    int e = gtid >> 3;
    int c = gtid & 7;
    if (e >= EE) return;
    int is64 = g_is64;
    long long s = ldidx(ei, e, is64);
    long long d = ldidx(ei, (long long)EE + e, is64);
    const float4* sp = reinterpret_cast<const float4*>(zc + s * ZS + src_col);
    float4 v0 = sp[c];
    float4 v1 = sp[c + 8];
    float* dp = zc + d * ZS + agg_col;
    red4(dp + c * 4, v0);
    red4(dp + 32 + c * 4, v1);
}

// ---------------- L0 MLP tail: h = relu( relu(agg+b1) @ W2 + b2 ), in place + stats ------
__global__ void __launch_bounds__(128) mlp0_kernel(
    float* zc, int col,
    const float* __restrict__ W2, const float* __restrict__ b1,
    const float* __restrict__ b2)
{
    __shared__ float Ws[64 * 64];
    __shared__ float Xs[64 * 68];
    const int tid = threadIdx.x, fg = tid & 7, ng = tid >> 3;
    const int node0 = blockIdx.x * 64;

    stage_w(Ws, W2, tid);
    {   // Xs = relu(agg + b1)
        int row = tid >> 1, part = tid & 1;
        int gn = node0 + row; if (gn >= NN) gn = NN - 1;
        const float4* src = reinterpret_cast<const float4*>(zc + (long long)gn * ZS + col);
        float4* dst = reinterpret_cast<float4*>(Xs + row * 68);
#pragma unroll
        for (int q = 0; q < 8; q++) {
            int c4 = part * 8 + q;
            float4 a = src[c4];
            float4 bb = reinterpret_cast<const float4*>(b1)[c4];
            dst[c4] = make_float4(fmaxf(a.x + bb.x, 0.0f), fmaxf(a.y + bb.y, 0.0f),
                                  fmaxf(a.z + bb.z, 0.0f), fmaxf(a.w + bb.w, 0.0f));
        }
    }
    __syncthreads();

    float acc[32];
    {
        float4 ba = reinterpret_cast<const float4*>(b2)[fg * 2];
        float4 bb = reinterpret_cast<const float4*>(b2)[fg * 2 + 1];
#pragma unroll
        for (int i = 0; i < 4; i++) {
            acc[i*8+0] = ba.x; acc[i*8+1] = ba.y; acc[i*8+2] = ba.z; acc[i*8+3] = ba.w;
            acc[i*8+4] = bb.x; acc[i*8+5] = bb.y; acc[i*8+6] = bb.z; acc[i*8+7] = bb.w;
        }
    }
    gemm_core(Xs, Ws, ng, fg, acc);

#pragma unroll
    for (int q = 0; q < 32; q++) acc[q] = fmaxf(acc[q], 0.0f);   // outer relu

#pragma unroll
    for (int i = 0; i < 4; i++) {
        int node = node0 + ng * 4 + i;
        if (node < NN) {
            float* row = zc + (long long)node * ZS + col;
            *reinterpret_cast<float4*>(row + fg * 8) =
                make_float4(acc[i*8+0], acc[i*8+1], acc[i*8+2], acc[i*8+3]);
            *reinterpret_cast<float4*>(row + fg * 8 + 4) =
                make_float4(acc[i*8+4], acc[i*8+5], acc[i*8+6], acc[i*8+7]);
        }
    }
    __syncthreads();               // Ws reads done chip... block-wide; reuse Ws as scratch
    stats_epi(Ws, acc, ng, fg, node0, tid);
}

// ---------------- L1/L2 fused MLP: h = relu( relu(agg@W1+b1) @ W2 + b2 ) + stats ----------
__global__ void __launch_bounds__(128) mlp2_kernel(
    float* zc, int in_col, int out_col,
    const float* __restrict__ W1, const float* __restrict__ b1,
    const float* __restrict__ W2, const float* __restrict__ b2)
{
    __shared__ float Ws[64 * 64];
    __shared__ float Xs[64 * 68];
    const int tid = threadIdx.x, fg = tid & 7, ng = tid >> 3;
    const int node0 = blockIdx.x * 64;

    stage_w(Ws, W1, tid);
    stage_x(Xs, zc + in_col, ZS, node0, tid);
    __syncthreads();

    // phase 1: acc = agg @ W1
    float acc[32];
#pragma unroll
    for (int q = 0; q < 32; q++) acc[q] = 0.0f;
    gemm_core(Xs, Ws, ng, fg, acc);
    __syncthreads();   // all phase-1 reads of Ws/Xs complete

    // h1 = relu(acc + b1) -> Xs (own rows), then stage W2
    {
        float4 ba = reinterpret_cast<const float4*>(b1)[fg * 2];
        float4 bb = reinterpret_cast<const float4*>(b1)[fg * 2 + 1];
#pragma unroll
        for (int i = 0; i < 4; i++) {
            float* hr = Xs + (ng * 4 + i) * 68 + fg * 8;
            *reinterpret_cast<float4*>(hr) =
                make_float4(fmaxf(acc[i*8+0]+ba.x,0.f), fmaxf(acc[i*8+1]+ba.y,0.f),
                            fmaxf(acc[i*8+2]+ba.z,0.f), fmaxf(acc[i*8+3]+ba.w,0.f));
            *reinterpret_cast<float4*>(hr + 4) =
                make_float4(fmaxf(acc[i*8+4]+bb.x,0.f), fmaxf(acc[i*8+5]+bb.y,0.f),
                            fmaxf(acc[i*8+6]+bb.z,0.f), fmaxf(acc[i*8+7]+bb.w,0.f));
        }
    }
    stage_w(Ws, W2, tid);
    __syncthreads();

    // phase 2: acc = h1 @ W2 + b2
    {
        float4 ba = reinterpret_cast<const float4*>(b2)[fg * 2];
        float4 bb = reinterpret_cast<const float4*>(b2)[fg * 2 + 1];
#pragma unroll
        for (int i = 0; i < 4; i++) {
            acc[i*8+0] = ba.x; acc[i*8+1] = ba.y; acc[i*8+2] = ba.z; acc[i*8+3] = ba.w;
            acc[i*8+4] = bb.x; acc[i*8+5] = bb.y; acc[i*8+6] = bb.z; acc[i*8+7] = bb.w;
        }
    }
    gemm_core(Xs, Ws, ng, fg, acc);

#pragma unroll
    for (int q = 0; q < 32; q++) acc[q] = fmaxf(acc[q], 0.0f);

#pragma unroll
    for (int i = 0; i < 4; i++) {
        int node = node0 + ng * 4 + i;
        if (node < NN) {
            float* row = zc + (long long)node * ZS + out_col;
            *reinterpret_cast<float4*>(row + fg * 8) =
                make_float4(acc[i*8+0], acc[i*8+1], acc[i*8+2], acc[i*8+3]);
            *reinterpret_cast<float4*>(row + fg * 8 + 4) =
                make_float4(acc[i*8+4], acc[i*8+5], acc[i*8+6], acc[i*8+7]);
        }
    }
    __syncthreads();
    stats_epi(Ws, acc, ng, fg, node0, tid);
}

// ---------------- BN finalize: scale/shift from stats; reset stats for next layer ----------
__global__ void bn_finalize_kernel(const float* __restrict__ gam, const float* __restrict__ bet) {
    int f = threadIdx.x;
    float mean = g_stats[f] * (1.0f / NN);
    float var = g_stats[64 + f] * (1.0f / NN) - mean * mean;
    var = fmaxf(var, 0.0f);
    float sc = gam[f] * rsqrtf(var + BN_EPS);
    g_ss[f] = sc;
    g_ss[64 + f] = bet[f] - mean * sc;
    g_stats[f] = 0.0f;
    g_stats[64 + f] = 0.0f;
}

// ---------------- BN apply (in place) + pool + optional copy (next layer's agg init) --------
__global__ void bn_apply_kernel(float* zc, int col_off, int copy_off,
                                const void* __restrict__ batch,
                                float* __restrict__ pool)
{
    int t = blockIdx.x * 256 + threadIdx.x;
    int n = t >> 4;
    int c = t & 15;
    if (n >= NN) return;
    int is64 = g_is64;
    float* row = zc + (long long)n * ZS;
    float4 h4 = *reinterpret_cast<float4*>(row + col_off + c * 4);
    float4 sc = *reinterpret_cast<const float4*>(g_ss + c * 4);
    float4 sh = *reinterpret_cast<const float4*>(g_ss + 64 + c * 4);
    float4 z;
    z.x = h4.x * sc.x + sh.x;
    z.y = h4.y * sc.y + sh.y;
    z.z = h4.z * sc.z + sh.z;
    z.w = h4.w * sc.w + sh.w;
    *reinterpret_cast<float4*>(row + col_off + c * 4) = z;
    if (copy_off >= 0)
        *reinterpret_cast<float4*>(row + copy_off + c * 4) = z;
    long long b = ldidx(batch, n, is64);
    red4(pool + b * ZS + col_off + c * 4, z);
}

// ---------------- launch ----------------
extern "C" void kernel_launch(void* const* d_in, const int* in_sizes, int n_in,
                              void* d_out, int out_size)
{
    const float* x     = (const float*)d_in[0];
    const void*  ei    = d_in[1];
    const void*  batch = d_in[2];
    const float* W1_0  = (const float*)d_in[3];
    const float* b1_0  = (const float*)d_in[4];
    const float* W2_0  = (const float*)d_in[5];
    const float* b2_0  = (const float*)d_in[6];
    const float* bn_g0 = (const float*)d_in[7];
    const float* bn_b0 = (const float*)d_in[8];
    const float* W1_r  = (const float*)d_in[9];
    const float* b1_r  = (const float*)d_in[10];
    const float* W2_r  = (const float*)d_in[11];
    const float* b2_r  = (const float*)d_in[12];
    const float* bn_gr = (const float*)d_in[13];
    const float* bn_br = (const float*)d_in[14];

    float* zc   = (float*)d_out;
    float* pool = zc + (long long)NN * ZS;

    const int gemm_grid = (NN + 63) / 64;          // 782
    const int scat_grid = (EE * 8) / 256;          // 25000
    const int bn_grid   = (NN * 16 + 255) / 256;   // 3125

    setup_kernel<<<96, 256>>>(pool, (const long long*)ei);

    // ---- layer 0: project first (y0 @ cols 64..127, agg init @ cols 0..63) ----
    gemm1_kernel<<<gemm_grid, 128>>>(x, W1_0, zc);
    scatter_kernel<<<scat_grid, 256>>>(zc, 64, 0, ei);
    mlp0_kernel<<<gemm_grid, 128>>>(zc, 0, W2_0, b1_0, b2_0);
    bn_finalize_kernel<<<1, 64>>>(bn_g0, bn_b0);
    bn_apply_kernel<<<bn_grid, 256>>>(zc, 0, 128, batch, pool);   // copy z0 -> cols 128

    // ---- layer 1: agg @ cols 128..191, output z1 @ cols 64..127 ----
    scatter_kernel<<<scat_grid, 256>>>(zc, 0, 128, ei);
    mlp2_kernel<<<gemm_grid, 128>>>(zc, 128, 64, W1_r, b1_r, W2_r, b2_r);
    bn_finalize_kernel<<<1, 64>>>(bn_gr, bn_br);
    bn_apply_kernel<<<bn_grid, 256>>>(zc, 64, 128, batch, pool);  // copy z1 -> cols 128

    // ---- layer 2: agg @ cols 128..191, output z2 @ cols 128..191 (in place) ----
    scatter_kernel<<<scat_grid, 256>>>(zc, 64, 128, ei);
    mlp2_kernel<<<gemm_grid, 128>>>(zc, 128, 128,
                                    W1_r + (size_t)HH * HH, b1_r + HH,
                                    W2_r + (size_t)HH * HH, b2_r + HH);
    bn_finalize_kernel<<<1, 64>>>(bn_gr + HH, bn_br + HH);
    bn_apply_kernel<<<bn_grid, 256>>>(zc, 128, -1, batch, pool);

    (void)in_sizes; (void)n_in; (void)out_size;
}